// round 4
// baseline (speedup 1.0000x reference)
#include <cuda_runtime.h>
#include <cuda_bf16.h>
#include <cstdint>

// ============================================================================
// DirectedEdgeEncoder on sm_103 (non-'a' target: mma.sync/ldmatrix only).
//
//   out[e] = relu( xW[row[e]] + edge_attr[e] @ W2^T )
//   xW[n]  = x[n] @ W1^T + b          (phase 0, per node)
//
// GEMMs: [M x 64] @ [64 x 128] via m16n8k16 bf16, 3-term hi/lo split.
// Physical tiles store only [hi | lo] (2 x 128B blocks per row); the virtual
// K=192 schedule picks blocks per 4-kstep segment:
//   seg0: A.hi x B.hi   seg1: A.hi x B.lo   seg2: A.lo x B.hi
//
// Round-4: dedup'd tiles (-33% STS, smem 66KB/CTA), 2 CTAs/SM (M_TILE=128,
// NT=256) for cross-CTA phase overlap.
// ============================================================================

#define M_TILE   128
#define NT       256
#define KSTEPS   12            // virtual K_aug = 192 / 16
#define AROW     256           // bytes per smem row (128 bf16: hi|lo blocks)

// smem layout (bytes)
#define SM_A     0                     // 128 x 256 = 32768
#define SM_B     32768                 // 128 x 256 = 32768
#define SM_IDX   65536                 // 128 x 4
#define SM_FLAG  (SM_IDX + 512)
#define SM_TOTAL (SM_FLAG + 16)        // 66064

__device__ float g_xW[50432 * 128];    // node @ W1^T + b   (25.8 MB)

// ---------------------------------------------------------------------------
__device__ __forceinline__ uint32_t smem_u32(const void* p) {
    uint32_t a;
    asm("{ .reg .u64 t; cvta.to.shared.u64 t, %1; cvt.u32.u64 %0, t; }"
        : "=r"(a) : "l"(p));
    return a;
}

__device__ __forceinline__ void ldmatrix_x4(uint32_t& r0, uint32_t& r1,
                                            uint32_t& r2, uint32_t& r3,
                                            uint32_t addr) {
    asm volatile("ldmatrix.sync.aligned.m8n8.x4.shared.b16 {%0,%1,%2,%3}, [%4];"
                 : "=r"(r0), "=r"(r1), "=r"(r2), "=r"(r3) : "r"(addr));
}

__device__ __forceinline__ void mma_bf16(float* c, const uint32_t* a,
                                         uint32_t b0, uint32_t b1) {
    asm volatile(
        "mma.sync.aligned.m16n8k16.row.col.f32.bf16.bf16.f32 "
        "{%0,%1,%2,%3}, {%4,%5,%6,%7}, {%8,%9}, {%0,%1,%2,%3};"
        : "+f"(c[0]), "+f"(c[1]), "+f"(c[2]), "+f"(c[3])
        : "r"(a[0]), "r"(a[1]), "r"(a[2]), "r"(a[3]), "r"(b0), "r"(b1));
}

__device__ __forceinline__ uint32_t pack_bf2(float a, float b) {
    __nv_bfloat162 t;
    t.x = __float2bfloat16_rn(a);
    t.y = __float2bfloat16_rn(b);
    return *reinterpret_cast<uint32_t*>(&t);
}

__device__ __forceinline__ void split4(float4 v, uint2& hi, uint2& lo) {
    float hx = __bfloat162float(__float2bfloat16_rn(v.x));
    float hy = __bfloat162float(__float2bfloat16_rn(v.y));
    float hz = __bfloat162float(__float2bfloat16_rn(v.z));
    float hw = __bfloat162float(__float2bfloat16_rn(v.w));
    hi.x = pack_bf2(v.x, v.y);
    hi.y = pack_bf2(v.z, v.w);
    lo.x = pack_bf2(v.x - hx, v.y - hy);
    lo.y = pack_bf2(v.z - hz, v.w - hw);
}

// swizzled 8B store: row r, 8-byte slot j (0..15) within 128B block blk.
__device__ __forceinline__ void sw_store8(char* base, int r, int blk, int j,
                                          uint2 v) {
    uint32_t off = (uint32_t)r * AROW + (uint32_t)blk * 128
                 + ((uint32_t)(((j >> 1) ^ (r & 7))) << 4) + ((j & 1) << 3);
    *(uint2*)(base + off) = v;
}

__device__ __forceinline__ void load_tile(float4* f, const float* __restrict__ src,
                                          int t, int M_total, int tid) {
    #pragma unroll
    for (int i = 0; i < 8; i++) {
        int idx = i * NT + tid;              // 0..2047
        int r = idx >> 4, j = idx & 15;
        int gr = t * M_TILE + r;
        if (gr >= M_total) gr = 0;           // clamp; stores guarded later
        f[i] = __ldg((const float4*)(src + (size_t)gr * 64 + j * 4));
    }
}

// ---------------------------------------------------------------------------
// PHASE 0: g_xW[r] = x[r] @ W[:, :64]^T + bias
// PHASE 1: out[e]  = relu( edge_attr[e] @ W[:, 64:]^T + g_xW[row[e]] )
// ---------------------------------------------------------------------------
template <int PHASE>
__global__ void __launch_bounds__(NT, 2)
gemm_kernel(float* __restrict__ out,
            const float* __restrict__ src,        // x or edge_attr [M,64]
            const void*  __restrict__ eidx,
            const float* __restrict__ W,          // [128,128]
            const float* __restrict__ bias,
            int M_total, int n_tiles) {
    extern __shared__ char smem[];
    const int tid  = threadIdx.x;
    const int wid  = tid >> 5;
    const int lane = tid & 31;
    const uint32_t sb = smem_u32(smem);

    // ---- dtype sniff for edge_index (int64 LE: odd 32-bit words all zero)
    if (PHASE == 1 && tid < 32) {
        unsigned v = 0;
        #pragma unroll
        for (int s = 0; s < 4; s++)
            v |= ((const unsigned*)eidx)[1 + 2 * (tid * 4 + s)];
        unsigned any = __ballot_sync(0xffffffffu, v != 0u);
        if (tid == 0) *(int*)(smem + SM_FLAG) = (any == 0u) ? 1 : 0;
    }

    // ---- build column-permuted B tile: physical [hi | lo]
    // smem row ns holds logical W column L(ns) so that accumulator fragments
    // of a thread cover 4 contiguous logical columns.
    {
        const float* Wp = W + (PHASE == 0 ? 0 : 64);
        #pragma unroll
        for (int i = 0; i < 8; i++) {
            int idx = i * NT + tid;              // 0..2047
            int ns = idx >> 4;                   // smem B row 0..127
            int j  = idx & 15;                   // 8B slot (4 floats)
            int nw   = ns >> 6;
            int rest = ns & 63;
            int ni = rest >> 3, pos = rest & 7;
            int q = pos >> 1, jj = pos & 1;
            int L = nw * 64 + ((ni >> 1) << 4) + (q << 2) + ((ni & 1) << 1) + jj;
            float4 v = *(const float4*)(Wp + L * 128 + j * 4);
            uint2 hi, lo;
            split4(v, hi, lo);
            sw_store8(smem + SM_B, ns, 0, j, hi);
            sw_store8(smem + SM_B, ns, 1, j, lo);
        }
    }

    // ---- prologue: load first tile into registers
    float4 f[8];
    if (blockIdx.x < n_tiles) load_tile(f, src, blockIdx.x, M_total, tid);
    __syncthreads();

    const int is64 = (PHASE == 1) ? *(const int*)(smem + SM_FLAG) : 0;

    const int mwarp = wid >> 1;              // 0..3  (32 rows each)
    const int nwarp = wid & 1;               // 0..1  (64 cols each)
    const int q     = lane & 3;

    const int aRow = mwarp * 32 + (lane & 7) + (((lane >> 3) & 1) << 3);
    const uint32_t aRowOff = sb + SM_A + (uint32_t)aRow * AROW;
    const int aRx = aRow & 7;
    const int aHalf = lane >> 4;
    const int bRowBase = nwarp * 64 + ((lane >> 4) << 3) + (lane & 7);
    const int bHalf = (lane >> 3) & 1;

    float4 bias4[4];
    if (PHASE == 0) {
        #pragma unroll
        for (int p = 0; p < 4; p++)
            bias4[p] = ((const float4*)bias)[nwarp * 16 + p * 4 + q];
    }

    int* idx_s = (int*)(smem + SM_IDX);

    for (int t = blockIdx.x; t < n_tiles; t += gridDim.x) {
        // ---- convert regs -> bf16 A tile: physical [hi | lo]
        {
            const int j = tid & 15;
            #pragma unroll
            for (int i = 0; i < 8; i++) {
                int r = i * 16 + (tid >> 4);
                uint2 hi, lo;
                split4(f[i], hi, lo);
                sw_store8(smem + SM_A, r, 0, j, hi);
                sw_store8(smem + SM_A, r, 1, j, lo);
            }
        }
        if (PHASE == 1 && tid < M_TILE) {
            int e = t * M_TILE + tid;
            int r = 0;
            if (e < M_total)
                r = is64 ? (int)((const long long*)eidx)[e]
                         : ((const int*)eidx)[e];
            idx_s[tid] = r;
        }
        __syncthreads();

        // ---- prefetch next tile into registers (hidden under MMA)
        int tn = t + gridDim.x;
        if (tn < n_tiles) load_tile(f, src, tn, M_total, tid);

        // ---- MMA: warp tile M32 x N64, virtual K = 192 over [hi|lo] blocks
        float acc[2][8][4];
        #pragma unroll
        for (int mi = 0; mi < 2; mi++)
            #pragma unroll
            for (int ni = 0; ni < 8; ni++)
                #pragma unroll
                for (int c = 0; c < 4; c++) acc[mi][ni][c] = 0.0f;

        #pragma unroll
        for (int ks = 0; ks < KSTEPS; ks++) {
            const int seg   = ks >> 2;
            const int ablk  = (seg == 2) ? 1 : 0;   // A: hi,hi,lo
            const int bblk  = (seg == 1) ? 1 : 0;   // B: hi,lo,hi
            const int cbase = (ks & 3) * 2;
            uint32_t a[2][4];
            #pragma unroll
            for (int mi = 0; mi < 2; mi++) {
                uint32_t addr = aRowOff + (uint32_t)mi * 16 * AROW
                    + (uint32_t)ablk * 128
                    + ((uint32_t)((cbase + aHalf) ^ aRx) << 4);
                ldmatrix_x4(a[mi][0], a[mi][1], a[mi][2], a[mi][3], addr);
            }
            uint32_t b[8][2];
            #pragma unroll
            for (int p = 0; p < 4; p++) {
                int brow = bRowBase + p * 16;
                uint32_t addr = sb + SM_B + (uint32_t)brow * AROW
                    + (uint32_t)bblk * 128
                    + ((uint32_t)((cbase + bHalf) ^ (brow & 7)) << 4);
                ldmatrix_x4(b[2*p][0], b[2*p][1], b[2*p+1][0], b[2*p+1][1],
                            addr);
            }
            #pragma unroll
            for (int mi = 0; mi < 2; mi++)
                #pragma unroll
                for (int ni = 0; ni < 8; ni++)
                    mma_bf16(acc[mi][ni], a[mi], b[ni][0], b[ni][1]);
        }

        // ---- epilogue: float4 fragments at logical cols nwarp*64+16p+4q
        const int colF4 = nwarp * 16 + q;
        #pragma unroll
        for (int mi = 0; mi < 2; mi++) {
            int r0 = mwarp * 32 + mi * 16 + (lane >> 2);
            int r1 = r0 + 8;
            if (PHASE == 1) {
                const float4* xp0 = (const float4*)
                    (g_xW + (size_t)idx_s[r0] * 128) + colF4;
                const float4* xp1 = (const float4*)
                    (g_xW + (size_t)idx_s[r1] * 128) + colF4;
                float4 g0[4], g1[4];
                #pragma unroll
                for (int p = 0; p < 4; p++) { g0[p] = __ldg(xp0 + p * 4);
                                              g1[p] = __ldg(xp1 + p * 4); }
                int rg0 = t * M_TILE + r0, rg1 = t * M_TILE + r1;
                float4* op0 = (float4*)out + (size_t)rg0 * 32 + colF4;
                float4* op1 = (float4*)out + (size_t)rg1 * 32 + colF4;
                #pragma unroll
                for (int p = 0; p < 4; p++) {
                    float4 o;
                    o.x = fmaxf(acc[mi][2*p][0]   + g0[p].x, 0.0f);
                    o.y = fmaxf(acc[mi][2*p][1]   + g0[p].y, 0.0f);
                    o.z = fmaxf(acc[mi][2*p+1][0] + g0[p].z, 0.0f);
                    o.w = fmaxf(acc[mi][2*p+1][1] + g0[p].w, 0.0f);
                    if (rg0 < M_total) op0[p * 4] = o;
                    o.x = fmaxf(acc[mi][2*p][2]   + g1[p].x, 0.0f);
                    o.y = fmaxf(acc[mi][2*p][3]   + g1[p].y, 0.0f);
                    o.z = fmaxf(acc[mi][2*p+1][2] + g1[p].z, 0.0f);
                    o.w = fmaxf(acc[mi][2*p+1][3] + g1[p].w, 0.0f);
                    if (rg1 < M_total) op1[p * 4] = o;
                }
            } else {
                int rg0 = t * M_TILE + r0, rg1 = t * M_TILE + r1;
                float4* op0 = (float4*)g_xW + (size_t)rg0 * 32 + colF4;
                float4* op1 = (float4*)g_xW + (size_t)rg1 * 32 + colF4;
                #pragma unroll
                for (int p = 0; p < 4; p++) {
                    float4 o;
                    o.x = acc[mi][2*p][0]   + bias4[p].x;
                    o.y = acc[mi][2*p][1]   + bias4[p].y;
                    o.z = acc[mi][2*p+1][0] + bias4[p].z;
                    o.w = acc[mi][2*p+1][1] + bias4[p].w;
                    if (rg0 < M_total) op0[p * 4] = o;
                    o.x = acc[mi][2*p][2]   + bias4[p].x;
                    o.y = acc[mi][2*p][3]   + bias4[p].y;
                    o.z = acc[mi][2*p+1][2] + bias4[p].z;
                    o.w = acc[mi][2*p+1][3] + bias4[p].w;
                    if (rg1 < M_total) op1[p * 4] = o;
                }
            }
        }
        __syncthreads();   // all reads of A done before next conversion
    }
}

// ---------------------------------------------------------------------------
extern "C" void kernel_launch(void* const* d_in, const int* in_sizes, int n_in,
                              void* d_out, int out_size) {
    const float* x         = (const float*)d_in[0];
    const float* edge_attr = (const float*)d_in[1];
    const void*  eidx      = d_in[2];
    const float* W         = (const float*)d_in[3];
    const float* bias      = (const float*)d_in[4];
    float* out             = (float*)d_out;

    const int Nn = in_sizes[0] / 64;
    const int E  = in_sizes[1] / 64;
    const int tiles0 = (Nn + M_TILE - 1) / M_TILE;
    const int tiles1 = (E  + M_TILE - 1) / M_TILE;

    cudaFuncSetAttribute(gemm_kernel<0>,
                         cudaFuncAttributeMaxDynamicSharedMemorySize, SM_TOTAL);
    cudaFuncSetAttribute(gemm_kernel<1>,
                         cudaFuncAttributeMaxDynamicSharedMemorySize, SM_TOTAL);

    const int maxg = 304;                     // 152 SMs x 2 CTAs
    int grid0 = tiles0 < maxg ? tiles0 : maxg;
    gemm_kernel<0><<<grid0, NT, SM_TOTAL>>>(nullptr, x, eidx, W, bias,
                                            Nn, tiles0);
    int grid1 = tiles1 < maxg ? tiles1 : maxg;
    gemm_kernel<1><<<grid1, NT, SM_TOTAL>>>(out, edge_attr, eidx, W, bias,
                                            E, tiles1);
}

// round 5
// speedup vs baseline: 1.0419x; 1.0419x over previous
#include <cuda_runtime.h>
#include <cuda_bf16.h>
#include <cstdint>

// ============================================================================
// DirectedEdgeEncoder on sm_103 (non-'a' target: mma.sync/ldmatrix only).
//
//   out[e] = relu( xW[row[e]] + edge_attr[e] @ W2^T )
//   xW[n]  = x[n] @ W1^T + b          (phase 0, per node)
//
// GEMMs: [M x 64] @ [64 x 128] via m16n8k16 bf16, 3-term hi/lo split.
// Physical tiles store [hi | lo] (2 x 128B blocks/row); virtual K=192:
//   seg0: A.hi x B.hi   seg1: A.hi x B.lo   seg2: A.lo x B.hi
//
// Round-5: 152 CTAs x 512 thr (protect g_xW L2 residency), warp tile M64xN32,
// B.hi fragments hoisted to registers (loop-invariant), cp.async staged input.
// ============================================================================

#define M_TILE   256
#define NT       512
#define KSTEPS   12
#define AROW     256            // bytes per smem row (128 bf16: hi|lo)

// smem layout (bytes)
#define SM_STAGE 0                       // 256 x 64 fp32      (65536)
#define SM_A     65536                   // 256 x 256 B        (65536)
#define SM_B     131072                  // 128 x 256 B        (32768)
#define SM_IDX   (131072 + 32768)        // 256 int            (1024)
#define SM_FLAG  (SM_IDX + 1024)
#define SM_TOTAL (SM_FLAG + 16)          // 164880

__device__ float g_xW[50432 * 128];      // node @ W1^T + b    (25.8 MB)

// ---------------------------------------------------------------------------
__device__ __forceinline__ uint32_t smem_u32(const void* p) {
    uint32_t a;
    asm("{ .reg .u64 t; cvta.to.shared.u64 t, %1; cvt.u32.u64 %0, t; }"
        : "=r"(a) : "l"(p));
    return a;
}

__device__ __forceinline__ void cp_async16(uint32_t dst, const void* src) {
    asm volatile("cp.async.cg.shared.global [%0], [%1], 16;"
                 :: "r"(dst), "l"(src) : "memory");
}
__device__ __forceinline__ void cp_commit() {
    asm volatile("cp.async.commit_group;" ::: "memory");
}
__device__ __forceinline__ void cp_wait_all() {
    asm volatile("cp.async.wait_all;" ::: "memory");
}

__device__ __forceinline__ void ldmatrix_x4(uint32_t& r0, uint32_t& r1,
                                            uint32_t& r2, uint32_t& r3,
                                            uint32_t addr) {
    asm volatile("ldmatrix.sync.aligned.m8n8.x4.shared.b16 {%0,%1,%2,%3}, [%4];"
                 : "=r"(r0), "=r"(r1), "=r"(r2), "=r"(r3) : "r"(addr));
}

__device__ __forceinline__ void mma_bf16(float* c, const uint32_t* a,
                                         uint32_t b0, uint32_t b1) {
    asm volatile(
        "mma.sync.aligned.m16n8k16.row.col.f32.bf16.bf16.f32 "
        "{%0,%1,%2,%3}, {%4,%5,%6,%7}, {%8,%9}, {%0,%1,%2,%3};"
        : "+f"(c[0]), "+f"(c[1]), "+f"(c[2]), "+f"(c[3])
        : "r"(a[0]), "r"(a[1]), "r"(a[2]), "r"(a[3]), "r"(b0), "r"(b1));
}

__device__ __forceinline__ uint32_t pack_bf2(float a, float b) {
    __nv_bfloat162 t;
    t.x = __float2bfloat16_rn(a);
    t.y = __float2bfloat16_rn(b);
    return *reinterpret_cast<uint32_t*>(&t);
}

__device__ __forceinline__ void split4(float4 v, uint2& hi, uint2& lo) {
    float hx = __bfloat162float(__float2bfloat16_rn(v.x));
    float hy = __bfloat162float(__float2bfloat16_rn(v.y));
    float hz = __bfloat162float(__float2bfloat16_rn(v.z));
    float hw = __bfloat162float(__float2bfloat16_rn(v.w));
    hi.x = pack_bf2(v.x, v.y);
    hi.y = pack_bf2(v.z, v.w);
    lo.x = pack_bf2(v.x - hx, v.y - hy);
    lo.y = pack_bf2(v.z - hz, v.w - hw);
}

// swizzled 8B store: row r, 8B slot j (0..15), 128B block blk
__device__ __forceinline__ void sw_store8(char* base, int r, int blk, int j,
                                          uint2 v) {
    uint32_t off = (uint32_t)r * AROW + (uint32_t)blk * 128
                 + ((uint32_t)(((j >> 1) ^ (r & 7))) << 4) + ((j & 1) << 3);
    *(uint2*)(base + off) = v;
}

__device__ __forceinline__ void stage_tile(uint32_t sb,
                                           const float* __restrict__ src,
                                           int t, int M_total, int tid) {
    #pragma unroll
    for (int i = 0; i < 8; i++) {
        int idx = i * NT + tid;              // 0..4095
        int r = idx >> 4, j = idx & 15;
        int gr = t * M_TILE + r;
        if (gr >= M_total) gr = 0;           // clamp; stores guarded later
        cp_async16(sb + SM_STAGE + idx * 16, src + (size_t)gr * 64 + j * 4);
    }
    cp_commit();
}

// ---------------------------------------------------------------------------
// PHASE 0: g_xW[r] = x[r] @ W[:, :64]^T + bias
// PHASE 1: out[e]  = relu( edge_attr[e] @ W[:, 64:]^T + g_xW[row[e]] )
// ---------------------------------------------------------------------------
template <int PHASE>
__global__ void __launch_bounds__(NT, 1)
gemm_kernel(float* __restrict__ out,
            const float* __restrict__ src,        // x or edge_attr [M,64]
            const void*  __restrict__ eidx,
            const float* __restrict__ W,          // [128,128]
            const float* __restrict__ bias,
            int M_total, int n_tiles) {
    extern __shared__ char smem[];
    const int tid  = threadIdx.x;
    const int wid  = tid >> 5;
    const int lane = tid & 31;
    const uint32_t sb = smem_u32(smem);

    // ---- dtype sniff for edge_index (int64 LE: odd 32-bit words all zero)
    if (PHASE == 1 && tid < 32) {
        unsigned v = 0;
        #pragma unroll
        for (int s = 0; s < 4; s++)
            v |= ((const unsigned*)eidx)[1 + 2 * (tid * 4 + s)];
        unsigned any = __ballot_sync(0xffffffffu, v != 0u);
        if (tid == 0) *(int*)(smem + SM_FLAG) = (any == 0u) ? 1 : 0;
    }

    // ---- build column-permuted B tile: physical [hi | lo]
    // smem row ns holds logical W column L(ns) such that each thread's
    // accumulator fragments form 4 contiguous logical columns (N32 warps).
    {
        const float* Wp = W + (PHASE == 0 ? 0 : 64);
        #pragma unroll
        for (int i = 0; i < 4; i++) {
            int idx = i * NT + tid;              // 0..2047
            int ns = idx >> 4;                   // B smem row 0..127
            int j  = idx & 15;
            int nwq  = ns >> 5;                  // N-warp 0..3
            int rest = ns & 31;
            int ni = rest >> 3, pos = rest & 7;
            int q = pos >> 1, jj = pos & 1;
            int L = nwq * 32 + ((ni >> 1) << 4) + (q << 2) + ((ni & 1) << 1) + jj;
            float4 v = *(const float4*)(Wp + L * 128 + j * 4);
            uint2 hi, lo;
            split4(v, hi, lo);
            sw_store8(smem + SM_B, ns, 0, j, hi);
            sw_store8(smem + SM_B, ns, 1, j, lo);
        }
    }

    // ---- stage first input tile
    if (blockIdx.x < n_tiles) stage_tile(sb, src, blockIdx.x, M_total, tid);
    __syncthreads();

    const int is64 = (PHASE == 1) ? *(const int*)(smem + SM_FLAG) : 0;

    const int mwarp = wid >> 2;              // 0..3  (64 rows each)
    const int nwarp = wid & 3;               // 0..3  (32 logical cols each)
    const int q     = lane & 3;

    const int aRow = mwarp * 64 + (lane & 7) + (((lane >> 3) & 1) << 3);
    const uint32_t aRowOff = sb + SM_A + (uint32_t)aRow * AROW;
    const int aRx = lane & 7;
    const int aHalf = lane >> 4;
    const int bRowBase = nwarp * 32 + ((lane >> 4) << 3) + (lane & 7);
    const int bHalf = (lane >> 3) & 1;

    // ---- hoist loop-invariant B.hi fragments (8 ldmatrix.x4, 32 regs)
    uint32_t bHi[4][8];
    #pragma unroll
    for (int c = 0; c < 4; c++) {
        #pragma unroll
        for (int p = 0; p < 2; p++) {
            int brow = bRowBase + p * 16;
            uint32_t addr = sb + SM_B + (uint32_t)brow * AROW
                + ((uint32_t)((2 * c + bHalf) ^ (brow & 7)) << 4);
            ldmatrix_x4(bHi[c][4*p], bHi[c][4*p+1], bHi[c][4*p+2], bHi[c][4*p+3],
                        addr);
        }
    }

    float4 bias4[2];
    if (PHASE == 0) {
        #pragma unroll
        for (int p = 0; p < 2; p++)
            bias4[p] = ((const float4*)bias)[nwarp * 8 + p * 4 + q];
    }

    int* idx_s = (int*)(smem + SM_IDX);

    for (int t = blockIdx.x; t < n_tiles; t += gridDim.x) {
        cp_wait_all();
        __syncthreads();                 // stage(t) ready; prev A reads done

        // ---- convert stage fp32 -> A tile [hi | lo]
        #pragma unroll
        for (int i = 0; i < 8; i++) {
            int idx = i * NT + tid;
            int r = idx >> 4, j = idx & 15;
            float4 v = *(const float4*)(smem + SM_STAGE + idx * 16);
            uint2 hi, lo;
            split4(v, hi, lo);
            sw_store8(smem + SM_A, r, 0, j, hi);
            sw_store8(smem + SM_A, r, 1, j, lo);
        }
        if (PHASE == 1 && tid < M_TILE) {
            int e = t * M_TILE + tid;
            int r = 0;
            if (e < M_total)
                r = is64 ? (int)((const long long*)eidx)[e]
                         : ((const int*)eidx)[e];
            idx_s[tid] = r;
        }
        __syncthreads();

        // ---- start streaming next tile (hidden under MMA)
        int tn = t + gridDim.x;
        if (tn < n_tiles) stage_tile(sb, src, tn, M_total, tid);

        // ---- MMA: warp tile M64 x N32, virtual K = 192
        float acc[4][4][4];
        #pragma unroll
        for (int mi = 0; mi < 4; mi++)
            #pragma unroll
            for (int ni = 0; ni < 4; ni++)
                #pragma unroll
                for (int c = 0; c < 4; c++) acc[mi][ni][c] = 0.0f;

        #pragma unroll
        for (int ks = 0; ks < KSTEPS; ks++) {
            const int seg  = ks >> 2;
            const int ablk = (seg == 2) ? 1 : 0;      // A: hi,hi,lo
            const int cc   = ks & 3;
            const int cbase = cc * 2;
            uint32_t a[4][4];
            #pragma unroll
            for (int mi = 0; mi < 4; mi++) {
                uint32_t addr = aRowOff + (uint32_t)mi * 16 * AROW
                    + (uint32_t)ablk * 128
                    + ((uint32_t)((cbase + aHalf) ^ aRx) << 4);
                ldmatrix_x4(a[mi][0], a[mi][1], a[mi][2], a[mi][3], addr);
            }
            uint32_t bl[4][2];
            const uint32_t (*bp)[2];
            if (seg == 1) {                            // B.lo: load per kstep
                #pragma unroll
                for (int p = 0; p < 2; p++) {
                    int brow = bRowBase + p * 16;
                    uint32_t addr = sb + SM_B + (uint32_t)brow * AROW + 128
                        + ((uint32_t)((cbase + bHalf) ^ (brow & 7)) << 4);
                    ldmatrix_x4(bl[2*p][0], bl[2*p][1], bl[2*p+1][0],
                                bl[2*p+1][1], addr);
                }
                bp = bl;
            } else {                                   // B.hi: hoisted
                bp = (const uint32_t (*)[2])&bHi[cc][0];
            }
            #pragma unroll
            for (int mi = 0; mi < 4; mi++)
                #pragma unroll
                for (int ni = 0; ni < 4; ni++)
                    mma_bf16(acc[mi][ni], a[mi], bp[ni][0], bp[ni][1]);
        }

        // ---- epilogue: float4 fragments at logical cols nwarp*32+16p+4q
        const int colF4 = nwarp * 8 + q;
        #pragma unroll
        for (int h = 0; h < 2; h++) {
            const int miA = 2 * h, miB = 2 * h + 1;
            int rA0 = mwarp * 64 + miA * 16 + (lane >> 2);
            int rA1 = rA0 + 8;
            int rB0 = rA0 + 16, rB1 = rA0 + 24;
            if (PHASE == 1) {
                float4 g[2][2][2];   // [mi sel][r sel][p]
                const int rows[2][2] = {{rA0, rA1}, {rB0, rB1}};
                #pragma unroll
                for (int m = 0; m < 2; m++)
                    #pragma unroll
                    for (int rr = 0; rr < 2; rr++) {
                        const float4* xp = (const float4*)
                            (g_xW + (size_t)idx_s[rows[m][rr]] * 128) + colF4;
                        g[m][rr][0] = __ldg(xp);
                        g[m][rr][1] = __ldg(xp + 4);
                    }
                #pragma unroll
                for (int m = 0; m < 2; m++) {
                    const int mi = miA + m;
                    #pragma unroll
                    for (int rr = 0; rr < 2; rr++) {
                        int rg = t * M_TILE + rows[m][rr];
                        if (rg >= M_total) continue;
                        float4* op = (float4*)out + (size_t)rg * 32 + colF4;
                        #pragma unroll
                        for (int p = 0; p < 2; p++) {
                            float4 o;
                            o.x = fmaxf(acc[mi][2*p][2*rr+0]   + g[m][rr][p].x, 0.0f);
                            o.y = fmaxf(acc[mi][2*p][2*rr+1]   + g[m][rr][p].y, 0.0f);
                            o.z = fmaxf(acc[mi][2*p+1][2*rr+0] + g[m][rr][p].z, 0.0f);
                            o.w = fmaxf(acc[mi][2*p+1][2*rr+1] + g[m][rr][p].w, 0.0f);
                            op[p * 4] = o;
                        }
                    }
                }
            } else {
                const int rows[2][2] = {{rA0, rA1}, {rB0, rB1}};
                #pragma unroll
                for (int m = 0; m < 2; m++) {
                    const int mi = miA + m;
                    #pragma unroll
                    for (int rr = 0; rr < 2; rr++) {
                        int rg = t * M_TILE + rows[m][rr];
                        if (rg >= M_total) continue;
                        float4* op = (float4*)g_xW + (size_t)rg * 32 + colF4;
                        #pragma unroll
                        for (int p = 0; p < 2; p++) {
                            float4 o;
                            o.x = acc[mi][2*p][2*rr+0]   + bias4[p].x;
                            o.y = acc[mi][2*p][2*rr+1]   + bias4[p].y;
                            o.z = acc[mi][2*p+1][2*rr+0] + bias4[p].z;
                            o.w = acc[mi][2*p+1][2*rr+1] + bias4[p].w;
                            op[p * 4] = o;
                        }
                    }
                }
            }
        }
    }
}

// ---------------------------------------------------------------------------
extern "C" void kernel_launch(void* const* d_in, const int* in_sizes, int n_in,
                              void* d_out, int out_size) {
    const float* x         = (const float*)d_in[0];
    const float* edge_attr = (const float*)d_in[1];
    const void*  eidx      = d_in[2];
    const float* W         = (const float*)d_in[3];
    const float* bias      = (const float*)d_in[4];
    float* out             = (float*)d_out;

    const int Nn = in_sizes[0] / 64;
    const int E  = in_sizes[1] / 64;
    const int tiles0 = (Nn + M_TILE - 1) / M_TILE;
    const int tiles1 = (E  + M_TILE - 1) / M_TILE;

    cudaFuncSetAttribute(gemm_kernel<0>,
                         cudaFuncAttributeMaxDynamicSharedMemorySize, SM_TOTAL);
    cudaFuncSetAttribute(gemm_kernel<1>,
                         cudaFuncAttributeMaxDynamicSharedMemorySize, SM_TOTAL);

    int grid0 = tiles0 < 152 ? tiles0 : 152;
    gemm_kernel<0><<<grid0, NT, SM_TOTAL>>>(nullptr, x, eidx, W, bias,
                                            Nn, tiles0);
    int grid1 = tiles1 < 152 ? tiles1 : 152;
    gemm_kernel<1><<<grid1, NT, SM_TOTAL>>>(out, edge_attr, eidx, W, bias,
                                            E, tiles1);
}

// round 7
// speedup vs baseline: 1.2650x; 1.2141x over previous
#include <cuda_runtime.h>
#include <cuda_bf16.h>
#include <cstdint>

// ============================================================================
// DirectedEdgeEncoder on sm_103 (non-'a' target: mma.sync/ldmatrix only).
//
//   out[e] = relu( xW[row[e]] + edge_attr[e] @ W2^T )
//   xW[n]  = x[n] @ W1^T + b          (phase 0, per node)
//
// GEMMs: [M x 64] @ [64 x 128] via m16n8k16 bf16, 3-term hi/lo split.
// Physical tiles store [hi | lo] (2 x 128B blocks/row); virtual K=192:
//   seg0: A.hi x B.hi   seg1: A.hi x B.lo   seg2: A.lo x B.hi
//
// Round-6: R3 skeleton (152 CTAs, M_TILE=256, warp tile M32xN64, LDG->reg
// prefetch) + per-pair pipelines: A rows partitioned by mwarp, pair-scoped
// bar.sync instead of CTA __syncthreads -> 8 independent pipelines per SM.
// ============================================================================

#define M_TILE   256
#define NT       512
#define KSTEPS   12            // virtual K = 192 / 16
#define AROW     256           // bytes per smem row (128 bf16: hi|lo)

// smem layout (bytes)
#define SM_A     0                     // 256 x 256 = 65536
#define SM_B     65536                 // 128 x 256 = 32768
#define SM_FLAG  (65536 + 32768)
#define SM_TOTAL (SM_FLAG + 16)        // 98320

__device__ float g_xW[50432 * 128];    // node @ W1^T + b   (25.8 MB)

// ---------------------------------------------------------------------------
__device__ __forceinline__ uint32_t smem_u32(const void* p) {
    uint32_t a;
    asm("{ .reg .u64 t; cvta.to.shared.u64 t, %1; cvt.u32.u64 %0, t; }"
        : "=r"(a) : "l"(p));
    return a;
}

#define BAR_PAIR(id) asm volatile("bar.sync %0, 64;" :: "r"(id) : "memory")

__device__ __forceinline__ void ldmatrix_x4(uint32_t& r0, uint32_t& r1,
                                            uint32_t& r2, uint32_t& r3,
                                            uint32_t addr) {
    asm volatile("ldmatrix.sync.aligned.m8n8.x4.shared.b16 {%0,%1,%2,%3}, [%4];"
                 : "=r"(r0), "=r"(r1), "=r"(r2), "=r"(r3) : "r"(addr));
}

__device__ __forceinline__ void mma_bf16(float* c, const uint32_t* a,
                                         uint32_t b0, uint32_t b1) {
    asm volatile(
        "mma.sync.aligned.m16n8k16.row.col.f32.bf16.bf16.f32 "
        "{%0,%1,%2,%3}, {%4,%5,%6,%7}, {%8,%9}, {%0,%1,%2,%3};"
        : "+f"(c[0]), "+f"(c[1]), "+f"(c[2]), "+f"(c[3])
        : "r"(a[0]), "r"(a[1]), "r"(a[2]), "r"(a[3]), "r"(b0), "r"(b1));
}

__device__ __forceinline__ uint32_t pack_bf2(float a, float b) {
    __nv_bfloat162 t;
    t.x = __float2bfloat16_rn(a);
    t.y = __float2bfloat16_rn(b);
    return *reinterpret_cast<uint32_t*>(&t);
}

__device__ __forceinline__ void split4(float4 v, uint2& hi, uint2& lo) {
    float hx = __bfloat162float(__float2bfloat16_rn(v.x));
    float hy = __bfloat162float(__float2bfloat16_rn(v.y));
    float hz = __bfloat162float(__float2bfloat16_rn(v.z));
    float hw = __bfloat162float(__float2bfloat16_rn(v.w));
    hi.x = pack_bf2(v.x, v.y);
    hi.y = pack_bf2(v.z, v.w);
    lo.x = pack_bf2(v.x - hx, v.y - hy);
    lo.y = pack_bf2(v.z - hz, v.w - hw);
}

// swizzled 8B store: row r, 128B block blk (0/1), 8B slot j (0..15)
__device__ __forceinline__ void sw_store8(char* base, int r, int blk, int j,
                                          uint2 v) {
    uint32_t off = (uint32_t)r * AROW + (uint32_t)blk * 128
                 + ((uint32_t)(((j >> 1) ^ (r & 7))) << 4) + ((j & 1) << 3);
    *(uint2*)(base + off) = v;
}

// per-pair prefetch: pair owns A rows [mwarp*32, +32); 8 float4 per thread
__device__ __forceinline__ void prefetch_pair(float4* f,
                                              const float* __restrict__ src,
                                              int t, int M_total,
                                              int mwarp, int wtid) {
    #pragma unroll
    for (int i = 0; i < 8; i++) {
        int c = i * 64 + wtid;               // 0..511
        int row = mwarp * 32 + (c >> 4);
        int j = c & 15;
        int gr = t * M_TILE + row;
        if (gr >= M_total) gr = 0;           // clamp; stores guarded later
        f[i] = __ldg((const float4*)(src + (size_t)gr * 64 + j * 4));
    }
}

__device__ __forceinline__ int ldidx(const void* eidx, int is64, long long e) {
    return is64 ? (int)__ldg((const long long*)eidx + e)
                : __ldg((const int*)eidx + e);
}

// ---------------------------------------------------------------------------
// PHASE 0: g_xW[r] = x[r] @ W[:, :64]^T + bias
// PHASE 1: out[e]  = relu( edge_attr[e] @ W[:, 64:]^T + g_xW[row[e]] )
// ---------------------------------------------------------------------------
template <int PHASE>
__global__ void __launch_bounds__(NT, 1)
gemm_kernel(float* __restrict__ out,
            const float* __restrict__ src,        // x or edge_attr [M,64]
            const void*  __restrict__ eidx,
            const float* __restrict__ W,          // [128,128]
            const float* __restrict__ bias,
            int M_total, int n_tiles) {
    extern __shared__ char smem[];
    const int tid  = threadIdx.x;
    const int wid  = tid >> 5;
    const int lane = tid & 31;
    const uint32_t sb = smem_u32(smem);

    // ---- dtype sniff for edge_index (int64 LE: odd 32-bit words all zero)
    if (PHASE == 1 && tid < 32) {
        unsigned v = 0;
        #pragma unroll
        for (int s = 0; s < 4; s++)
            v |= ((const unsigned*)eidx)[1 + 2 * (tid * 4 + s)];
        unsigned any = __ballot_sync(0xffffffffu, v != 0u);
        if (tid == 0) *(int*)(smem + SM_FLAG) = (any == 0u) ? 1 : 0;
    }

    // ---- build column-permuted B tile: physical [hi | lo]
    // smem row ns holds logical W column L(ns) so each thread's accumulator
    // fragments form 4 contiguous logical columns (N64 warp tiles).
    {
        const float* Wp = W + (PHASE == 0 ? 0 : 64);
        #pragma unroll
        for (int i = 0; i < 4; i++) {
            int idx = i * NT + tid;              // 0..2047
            int ns = idx >> 4;                   // B smem row 0..127
            int j  = idx & 15;
            int nw   = ns >> 6;
            int rest = ns & 63;
            int ni = rest >> 3, pos = rest & 7;
            int q = pos >> 1, jj = pos & 1;
            int L = nw * 64 + ((ni >> 1) << 4) + (q << 2) + ((ni & 1) << 1) + jj;
            float4 v = *(const float4*)(Wp + L * 128 + j * 4);
            uint2 hi, lo;
            split4(v, hi, lo);
            sw_store8(smem + SM_B, ns, 0, j, hi);
            sw_store8(smem + SM_B, ns, 1, j, lo);
        }
    }

    const int mwarp = wid >> 1;              // 0..7 : pair id, owns 32 A rows
    const int nwarp = wid & 1;               // 0..1
    const int wtid  = tid & 63;              // thread within pair
    const int q     = lane & 3;
    const int barid = mwarp + 1;

    // ---- prologue: prefetch first tile (own rows)
    float4 f[8];
    if (blockIdx.x < n_tiles)
        prefetch_pair(f, src, blockIdx.x, M_total, mwarp, wtid);

    __syncthreads();     // B tile + sniff flag ready; only CTA-wide sync
    const int is64 = (PHASE == 1) ? *(const int*)(smem + SM_FLAG) : 0;

    const int aRow = mwarp * 32 + (lane & 7) + (((lane >> 3) & 1) << 3);
    const uint32_t aRowOff = sb + SM_A + (uint32_t)aRow * AROW;
    const int aRx = lane & 7;
    const int aHalf = lane >> 4;
    const int bRowBase = nwarp * 64 + ((lane >> 4) << 3) + (lane & 7);
    const int bHalf = (lane >> 3) & 1;

    float4 bias4[4];
    if (PHASE == 0) {
        #pragma unroll
        for (int p = 0; p < 4; p++)
            bias4[p] = ((const float4*)bias)[nwarp * 16 + p * 4 + q];
    }

    for (int t = blockIdx.x; t < n_tiles; t += gridDim.x) {
        BAR_PAIR(barid);   // partner's ldmatrix of previous tile done

        // ---- convert own rows: regs -> A tile [hi | lo]
        #pragma unroll
        for (int i = 0; i < 8; i++) {
            int c = i * 64 + wtid;
            int row = mwarp * 32 + (c >> 4);
            int j = c & 15;
            uint2 hi, lo;
            split4(f[i], hi, lo);
            sw_store8(smem + SM_A, row, 0, j, hi);
            sw_store8(smem + SM_A, row, 1, j, lo);
        }
        BAR_PAIR(barid);   // pair's A rows visible to both warps

        // ---- prefetch next tile (own rows), hidden under MMA
        int tn = t + gridDim.x;
        if (tn < n_tiles) prefetch_pair(f, src, tn, M_total, mwarp, wtid);

        // ---- MMA: warp tile M32 x N64, virtual K = 192 over [hi|lo]
        float acc[2][8][4];
        #pragma unroll
        for (int mi = 0; mi < 2; mi++)
            #pragma unroll
            for (int ni = 0; ni < 8; ni++)
                #pragma unroll
                for (int c = 0; c < 4; c++) acc[mi][ni][c] = 0.0f;

        #pragma unroll
        for (int ks = 0; ks < KSTEPS; ks++) {
            const int seg  = ks >> 2;
            const int ablk = (seg == 2) ? 1 : 0;   // A: hi,hi,lo
            const int bblk = (seg == 1) ? 1 : 0;   // B: hi,lo,hi
            const int cbase = (ks & 3) * 2;
            uint32_t a[2][4];
            #pragma unroll
            for (int mi = 0; mi < 2; mi++) {
                uint32_t addr = aRowOff + (uint32_t)mi * 16 * AROW
                    + (uint32_t)ablk * 128
                    + ((uint32_t)((cbase + aHalf) ^ aRx) << 4);
                ldmatrix_x4(a[mi][0], a[mi][1], a[mi][2], a[mi][3], addr);
            }
            uint32_t b[8][2];
            #pragma unroll
            for (int p = 0; p < 4; p++) {
                int brow = bRowBase + p * 16;
                uint32_t addr = sb + SM_B + (uint32_t)brow * AROW
                    + (uint32_t)bblk * 128
                    + ((uint32_t)((cbase + bHalf) ^ (brow & 7)) << 4);
                ldmatrix_x4(b[2*p][0], b[2*p][1], b[2*p+1][0], b[2*p+1][1],
                            addr);
            }
            #pragma unroll
            for (int mi = 0; mi < 2; mi++)
                #pragma unroll
                for (int ni = 0; ni < 8; ni++)
                    mma_bf16(acc[mi][ni], a[mi], b[ni][0], b[ni][1]);
        }

        // ---- epilogue: float4 fragments at logical cols nwarp*64+16p+4q
        const int colF4 = nwarp * 16 + q;
        #pragma unroll
        for (int mi = 0; mi < 2; mi++) {
            int r0 = mwarp * 32 + mi * 16 + (lane >> 2);
            int r1 = r0 + 8;
            long long rg0 = (long long)t * M_TILE + r0;
            long long rg1 = (long long)t * M_TILE + r1;
            bool v0 = rg0 < M_total, v1 = rg1 < M_total;
            if (PHASE == 1) {
                int n0 = v0 ? ldidx(eidx, is64, rg0) : 0;
                int n1 = v1 ? ldidx(eidx, is64, rg1) : 0;
                const float4* xp0 = (const float4*)(g_xW + (size_t)n0 * 128)
                                    + colF4;
                const float4* xp1 = (const float4*)(g_xW + (size_t)n1 * 128)
                                    + colF4;
                float4 g0[4], g1[4];
                #pragma unroll
                for (int p = 0; p < 4; p++) { g0[p] = __ldg(xp0 + p * 4);
                                              g1[p] = __ldg(xp1 + p * 4); }
                float4* op0 = (float4*)out + (size_t)rg0 * 32 + colF4;
                float4* op1 = (float4*)out + (size_t)rg1 * 32 + colF4;
                #pragma unroll
                for (int p = 0; p < 4; p++) {
                    float4 o;
                    o.x = fmaxf(acc[mi][2*p][0]   + g0[p].x, 0.0f);
                    o.y = fmaxf(acc[mi][2*p][1]   + g0[p].y, 0.0f);
                    o.z = fmaxf(acc[mi][2*p+1][0] + g0[p].z, 0.0f);
                    o.w = fmaxf(acc[mi][2*p+1][1] + g0[p].w, 0.0f);
                    if (v0) op0[p * 4] = o;
                    o.x = fmaxf(acc[mi][2*p][2]   + g1[p].x, 0.0f);
                    o.y = fmaxf(acc[mi][2*p][3]   + g1[p].y, 0.0f);
                    o.z = fmaxf(acc[mi][2*p+1][2] + g1[p].z, 0.0f);
                    o.w = fmaxf(acc[mi][2*p+1][3] + g1[p].w, 0.0f);
                    if (v1) op1[p * 4] = o;
                }
            } else {
                float4* op0 = (float4*)g_xW + (size_t)rg0 * 32 + colF4;
                float4* op1 = (float4*)g_xW + (size_t)rg1 * 32 + colF4;
                #pragma unroll
                for (int p = 0; p < 4; p++) {
                    float4 o;
                    o.x = acc[mi][2*p][0]   + bias4[p].x;
                    o.y = acc[mi][2*p][1]   + bias4[p].y;
                    o.z = acc[mi][2*p+1][0] + bias4[p].z;
                    o.w = acc[mi][2*p+1][1] + bias4[p].w;
                    if (v0) op0[p * 4] = o;
                    o.x = acc[mi][2*p][2]   + bias4[p].x;
                    o.y = acc[mi][2*p][3]   + bias4[p].y;
                    o.z = acc[mi][2*p+1][2] + bias4[p].z;
                    o.w = acc[mi][2*p+1][3] + bias4[p].w;
                    if (v1) op1[p * 4] = o;
                }
            }
        }
    }
}

// ---------------------------------------------------------------------------
extern "C" void kernel_launch(void* const* d_in, const int* in_sizes, int n_in,
                              void* d_out, int out_size) {
    const float* x         = (const float*)d_in[0];
    const float* edge_attr = (const float*)d_in[1];
    const void*  eidx      = d_in[2];
    const float* W         = (const float*)d_in[3];
    const float* bias      = (const float*)d_in[4];
    float* out             = (float*)d_out;

    const int Nn = in_sizes[0] / 64;
    const int E  = in_sizes[1] / 64;
    const int tiles0 = (Nn + M_TILE - 1) / M_TILE;
    const int tiles1 = (E  + M_TILE - 1) / M_TILE;

    cudaFuncSetAttribute(gemm_kernel<0>,
                         cudaFuncAttributeMaxDynamicSharedMemorySize, SM_TOTAL);
    cudaFuncSetAttribute(gemm_kernel<1>,
                         cudaFuncAttributeMaxDynamicSharedMemorySize, SM_TOTAL);

    int grid0 = tiles0 < 152 ? tiles0 : 152;
    gemm_kernel<0><<<grid0, NT, SM_TOTAL>>>(nullptr, x, eidx, W, bias,
                                            Nn, tiles0);
    int grid1 = tiles1 < 152 ? tiles1 : 152;
    gemm_kernel<1><<<grid1, NT, SM_TOTAL>>>(out, edge_attr, eidx, W, bias,
                                            E, tiles1);
}

// round 8
// speedup vs baseline: 1.6223x; 1.2824x over previous
#include <cuda_runtime.h>
#include <cuda_bf16.h>
#include <cstdint>

// ============================================================================
// DirectedEdgeEncoder on sm_103 (non-'a' target: mma.sync/ldmatrix only).
//
//   out[e] = relu( xW[row[e]] + edge_attr[e] @ W2^T )
//   xW[n]  = x[n] @ W1^T + b          (phase 0, per node)
//
// GEMMs: [M x 64] @ [64 x 128] via m16n8k16 bf16, 3-term hi/lo split.
// Physical tiles store [hi | lo] (2 x 128B blocks/row); per K-chunk cc the
// loop loads A.hi/A.lo/B.hi/B.lo fragments once and issues:
//   acc += A.hi x B.hi;  acc += A.lo x B.hi;  acc += A.hi x B.lo
//
// Round-7: R3 lockstep skeleton (152 CTAs x 512 thr, M_TILE 256, CTA syncs,
// LDG->reg prefetch) + dedup tiles (-33% STS) + cc-outer loop (-33% ldmatrix).
// ============================================================================

#define M_TILE   256
#define NT       512
#define AROW     256           // bytes per smem row (128 bf16: hi|lo)

// smem layout (bytes)
#define SM_A     0                     // 256 x 256 = 65536
#define SM_B     65536                 // 128 x 256 = 32768
#define SM_IDX   (65536 + 32768)       // 256 int   = 1024
#define SM_FLAG  (SM_IDX + 1024)
#define SM_TOTAL (SM_FLAG + 16)        // 99344

__device__ float g_xW[50432 * 128];    // node @ W1^T + b   (25.8 MB)

// ---------------------------------------------------------------------------
__device__ __forceinline__ uint32_t smem_u32(const void* p) {
    uint32_t a;
    asm("{ .reg .u64 t; cvta.to.shared.u64 t, %1; cvt.u32.u64 %0, t; }"
        : "=r"(a) : "l"(p));
    return a;
}

__device__ __forceinline__ void ldmatrix_x4(uint32_t& r0, uint32_t& r1,
                                            uint32_t& r2, uint32_t& r3,
                                            uint32_t addr) {
    asm volatile("ldmatrix.sync.aligned.m8n8.x4.shared.b16 {%0,%1,%2,%3}, [%4];"
                 : "=r"(r0), "=r"(r1), "=r"(r2), "=r"(r3) : "r"(addr));
}

__device__ __forceinline__ void mma_bf16(float* c, const uint32_t* a,
                                         uint32_t b0, uint32_t b1) {
    asm volatile(
        "mma.sync.aligned.m16n8k16.row.col.f32.bf16.bf16.f32 "
        "{%0,%1,%2,%3}, {%4,%5,%6,%7}, {%8,%9}, {%0,%1,%2,%3};"
        : "+f"(c[0]), "+f"(c[1]), "+f"(c[2]), "+f"(c[3])
        : "r"(a[0]), "r"(a[1]), "r"(a[2]), "r"(a[3]), "r"(b0), "r"(b1));
}

__device__ __forceinline__ uint32_t pack_bf2(float a, float b) {
    __nv_bfloat162 t;
    t.x = __float2bfloat16_rn(a);
    t.y = __float2bfloat16_rn(b);
    return *reinterpret_cast<uint32_t*>(&t);
}

__device__ __forceinline__ void split4(float4 v, uint2& hi, uint2& lo) {
    float hx = __bfloat162float(__float2bfloat16_rn(v.x));
    float hy = __bfloat162float(__float2bfloat16_rn(v.y));
    float hz = __bfloat162float(__float2bfloat16_rn(v.z));
    float hw = __bfloat162float(__float2bfloat16_rn(v.w));
    hi.x = pack_bf2(v.x, v.y);
    hi.y = pack_bf2(v.z, v.w);
    lo.x = pack_bf2(v.x - hx, v.y - hy);
    lo.y = pack_bf2(v.z - hz, v.w - hw);
}

// swizzled 8B store: row r, 128B block blk (0/1), 8B slot j (0..15)
__device__ __forceinline__ void sw_store8(char* base, int r, int blk, int j,
                                          uint2 v) {
    uint32_t off = (uint32_t)r * AROW + (uint32_t)blk * 128
                 + ((uint32_t)(((j >> 1) ^ (r & 7))) << 4) + ((j & 1) << 3);
    *(uint2*)(base + off) = v;
}

__device__ __forceinline__ void load_tile(float4* f, const float* __restrict__ src,
                                          int t, int M_total, int tid) {
    #pragma unroll
    for (int i = 0; i < 8; i++) {
        int idx = i * NT + tid;              // 0..4095
        int r = idx >> 4, j = idx & 15;
        int gr = t * M_TILE + r;
        if (gr >= M_total) gr = 0;           // clamp; stores guarded later
        f[i] = __ldg((const float4*)(src + (size_t)gr * 64 + j * 4));
    }
}

// ---------------------------------------------------------------------------
// PHASE 0: g_xW[r] = x[r] @ W[:, :64]^T + bias
// PHASE 1: out[e]  = relu( edge_attr[e] @ W[:, 64:]^T + g_xW[row[e]] )
// ---------------------------------------------------------------------------
template <int PHASE>
__global__ void __launch_bounds__(NT, 1)
gemm_kernel(float* __restrict__ out,
            const float* __restrict__ src,        // x or edge_attr [M,64]
            const void*  __restrict__ eidx,
            const float* __restrict__ W,          // [128,128]
            const float* __restrict__ bias,
            int M_total, int n_tiles) {
    extern __shared__ char smem[];
    const int tid  = threadIdx.x;
    const int wid  = tid >> 5;
    const int lane = tid & 31;
    const uint32_t sb = smem_u32(smem);

    // ---- dtype sniff for edge_index (int64 LE: odd 32-bit words all zero)
    if (PHASE == 1 && tid < 32) {
        unsigned v = 0;
        #pragma unroll
        for (int s = 0; s < 4; s++)
            v |= ((const unsigned*)eidx)[1 + 2 * (tid * 4 + s)];
        unsigned any = __ballot_sync(0xffffffffu, v != 0u);
        if (tid == 0) *(int*)(smem + SM_FLAG) = (any == 0u) ? 1 : 0;
    }

    // ---- build column-permuted B tile: physical [hi | lo]
    // smem row ns holds logical W column L(ns) so each thread's accumulator
    // fragments form 4 contiguous logical columns.
    {
        const float* Wp = W + (PHASE == 0 ? 0 : 64);
        #pragma unroll
        for (int i = 0; i < 4; i++) {
            int idx = i * NT + tid;              // 0..2047
            int ns = idx >> 4;                   // B smem row 0..127
            int j  = idx & 15;
            int nw   = ns >> 6;
            int rest = ns & 63;
            int ni = rest >> 3, pos = rest & 7;
            int q = pos >> 1, jj = pos & 1;
            int L = nw * 64 + ((ni >> 1) << 4) + (q << 2) + ((ni & 1) << 1) + jj;
            float4 v = *(const float4*)(Wp + L * 128 + j * 4);
            uint2 hi, lo;
            split4(v, hi, lo);
            sw_store8(smem + SM_B, ns, 0, j, hi);
            sw_store8(smem + SM_B, ns, 1, j, lo);
        }
    }

    // ---- prologue: load first tile into registers
    float4 f[8];
    if (blockIdx.x < n_tiles) load_tile(f, src, blockIdx.x, M_total, tid);
    __syncthreads();

    const int is64 = (PHASE == 1) ? *(const int*)(smem + SM_FLAG) : 0;

    const int mwarp = wid >> 1;              // 0..7  (32 rows each)
    const int nwarp = wid & 1;               // 0..1  (64 cols each)
    const int q     = lane & 3;

    const int aRow = mwarp * 32 + (lane & 7) + (((lane >> 3) & 1) << 3);
    const uint32_t aRowOff = sb + SM_A + (uint32_t)aRow * AROW;
    const int aRx = aRow & 7;
    const int aHalf = lane >> 4;
    const int bRowBase = nwarp * 64 + ((lane >> 4) << 3) + (lane & 7);
    const int bHalf = (lane >> 3) & 1;

    float4 bias4[4];
    if (PHASE == 0) {
        #pragma unroll
        for (int p = 0; p < 4; p++)
            bias4[p] = ((const float4*)bias)[nwarp * 16 + p * 4 + q];
    }

    int* idx_s = (int*)(smem + SM_IDX);

    for (int t = blockIdx.x; t < n_tiles; t += gridDim.x) {
        // ---- convert regs -> A tile: physical [hi | lo]
        {
            const int j = tid & 15;
            #pragma unroll
            for (int i = 0; i < 8; i++) {
                int r = i * 32 + (tid >> 4);
                uint2 hi, lo;
                split4(f[i], hi, lo);
                sw_store8(smem + SM_A, r, 0, j, hi);
                sw_store8(smem + SM_A, r, 1, j, lo);
            }
        }
        if (PHASE == 1 && tid < M_TILE) {
            int e = t * M_TILE + tid;
            int r = 0;
            if (e < M_total)
                r = is64 ? (int)((const long long*)eidx)[e]
                         : ((const int*)eidx)[e];
            idx_s[tid] = r;
        }
        __syncthreads();

        // ---- MMA: warp tile M32 x N64; cc-outer, fragments loaded once
        float acc[2][8][4];
        #pragma unroll
        for (int mi = 0; mi < 2; mi++)
            #pragma unroll
            for (int ni = 0; ni < 8; ni++)
                #pragma unroll
                for (int c = 0; c < 4; c++) acc[mi][ni][c] = 0.0f;

        #pragma unroll
        for (int cc = 0; cc < 4; cc++) {
            const int cbase = cc * 2;
            // A.hi and A.lo fragments for this K-chunk
            uint32_t ah[2][4], al[2][4];
            #pragma unroll
            for (int mi = 0; mi < 2; mi++) {
                uint32_t base = aRowOff + (uint32_t)mi * 16 * AROW
                    + ((uint32_t)((cbase + aHalf) ^ aRx) << 4);
                ldmatrix_x4(ah[mi][0], ah[mi][1], ah[mi][2], ah[mi][3], base);
                ldmatrix_x4(al[mi][0], al[mi][1], al[mi][2], al[mi][3],
                            base + 128);
            }
            // B.hi fragments -> hi*hi and lo*hi
            uint32_t b[8][2];
            #pragma unroll
            for (int p = 0; p < 4; p++) {
                int brow = bRowBase + p * 16;
                uint32_t addr = sb + SM_B + (uint32_t)brow * AROW
                    + ((uint32_t)((cbase + bHalf) ^ (brow & 7)) << 4);
                ldmatrix_x4(b[2*p][0], b[2*p][1], b[2*p+1][0], b[2*p+1][1],
                            addr);
            }
            #pragma unroll
            for (int mi = 0; mi < 2; mi++)
                #pragma unroll
                for (int ni = 0; ni < 8; ni++)
                    mma_bf16(acc[mi][ni], ah[mi], b[ni][0], b[ni][1]);
            #pragma unroll
            for (int mi = 0; mi < 2; mi++)
                #pragma unroll
                for (int ni = 0; ni < 8; ni++)
                    mma_bf16(acc[mi][ni], al[mi], b[ni][0], b[ni][1]);
            // B.lo fragments -> hi*lo (reuse b registers)
            #pragma unroll
            for (int p = 0; p < 4; p++) {
                int brow = bRowBase + p * 16;
                uint32_t addr = sb + SM_B + (uint32_t)brow * AROW + 128
                    + ((uint32_t)((cbase + bHalf) ^ (brow & 7)) << 4);
                ldmatrix_x4(b[2*p][0], b[2*p][1], b[2*p+1][0], b[2*p+1][1],
                            addr);
            }
            #pragma unroll
            for (int mi = 0; mi < 2; mi++)
                #pragma unroll
                for (int ni = 0; ni < 8; ni++)
                    mma_bf16(acc[mi][ni], ah[mi], b[ni][0], b[ni][1]);
        }

        // ---- prefetch next tile (after MMA: f regs don't overlap fragments;
        //      LDG latency hidden under the epilogue gathers/stores)
        int tn = t + gridDim.x;
        if (tn < n_tiles) load_tile(f, src, tn, M_total, tid);

        // ---- epilogue: float4 fragments at logical cols nwarp*64+16p+4q
        const int colF4 = nwarp * 16 + q;
        #pragma unroll
        for (int mi = 0; mi < 2; mi++) {
            int r0 = mwarp * 32 + mi * 16 + (lane >> 2);
            int r1 = r0 + 8;
            if (PHASE == 1) {
                const float4* xp0 = (const float4*)
                    (g_xW + (size_t)idx_s[r0] * 128) + colF4;
                const float4* xp1 = (const float4*)
                    (g_xW + (size_t)idx_s[r1] * 128) + colF4;
                float4 g0[4], g1[4];
                #pragma unroll
                for (int p = 0; p < 4; p++) { g0[p] = __ldg(xp0 + p * 4);
                                              g1[p] = __ldg(xp1 + p * 4); }
                int rg0 = t * M_TILE + r0, rg1 = t * M_TILE + r1;
                float4* op0 = (float4*)out + (size_t)rg0 * 32 + colF4;
                float4* op1 = (float4*)out + (size_t)rg1 * 32 + colF4;
                #pragma unroll
                for (int p = 0; p < 4; p++) {
                    float4 o;
                    o.x = fmaxf(acc[mi][2*p][0]   + g0[p].x, 0.0f);
                    o.y = fmaxf(acc[mi][2*p][1]   + g0[p].y, 0.0f);
                    o.z = fmaxf(acc[mi][2*p+1][0] + g0[p].z, 0.0f);
                    o.w = fmaxf(acc[mi][2*p+1][1] + g0[p].w, 0.0f);
                    if (rg0 < M_total) op0[p * 4] = o;
                    o.x = fmaxf(acc[mi][2*p][2]   + g1[p].x, 0.0f);
                    o.y = fmaxf(acc[mi][2*p][3]   + g1[p].y, 0.0f);
                    o.z = fmaxf(acc[mi][2*p+1][2] + g1[p].z, 0.0f);
                    o.w = fmaxf(acc[mi][2*p+1][3] + g1[p].w, 0.0f);
                    if (rg1 < M_total) op1[p * 4] = o;
                }
            } else {
                int rg0 = t * M_TILE + r0, rg1 = t * M_TILE + r1;
                float4* op0 = (float4*)g_xW + (size_t)rg0 * 32 + colF4;
                float4* op1 = (float4*)g_xW + (size_t)rg1 * 32 + colF4;
                #pragma unroll
                for (int p = 0; p < 4; p++) {
                    float4 o;
                    o.x = acc[mi][2*p][0]   + bias4[p].x;
                    o.y = acc[mi][2*p][1]   + bias4[p].y;
                    o.z = acc[mi][2*p+1][0] + bias4[p].z;
                    o.w = acc[mi][2*p+1][1] + bias4[p].w;
                    if (rg0 < M_total) op0[p * 4] = o;
                    o.x = acc[mi][2*p][2]   + bias4[p].x;
                    o.y = acc[mi][2*p][3]   + bias4[p].y;
                    o.z = acc[mi][2*p+1][2] + bias4[p].z;
                    o.w = acc[mi][2*p+1][3] + bias4[p].w;
                    if (rg1 < M_total) op1[p * 4] = o;
                }
            }
        }
        __syncthreads();   // all reads of A done before next conversion
    }
}

// ---------------------------------------------------------------------------
extern "C" void kernel_launch(void* const* d_in, const int* in_sizes, int n_in,
                              void* d_out, int out_size) {
    const float* x         = (const float*)d_in[0];
    const float* edge_attr = (const float*)d_in[1];
    const void*  eidx      = d_in[2];
    const float* W         = (const float*)d_in[3];
    const float* bias      = (const float*)d_in[4];
    float* out             = (float*)d_out;

    const int Nn = in_sizes[0] / 64;
    const int E  = in_sizes[1] / 64;
    const int tiles0 = (Nn + M_TILE - 1) / M_TILE;
    const int tiles1 = (E  + M_TILE - 1) / M_TILE;

    cudaFuncSetAttribute(gemm_kernel<0>,
                         cudaFuncAttributeMaxDynamicSharedMemorySize, SM_TOTAL);
    cudaFuncSetAttribute(gemm_kernel<1>,
                         cudaFuncAttributeMaxDynamicSharedMemorySize, SM_TOTAL);

    int grid0 = tiles0 < 152 ? tiles0 : 152;
    gemm_kernel<0><<<grid0, NT, SM_TOTAL>>>(nullptr, x, eidx, W, bias,
                                            Nn, tiles0);
    int grid1 = tiles1 < 152 ? tiles1 : 152;
    gemm_kernel<1><<<grid1, NT, SM_TOTAL>>>(out, edge_attr, eidx, W, bias,
                                            E, tiles1);
}